// round 14
// baseline (speedup 1.0000x reference)
#include <cuda_runtime.h>
#include <cuda_fp16.h>
#include <cstdint>
#include <math.h>

#define S_LEN 4096
#define DIM   128
#define BQ    64
#define BK    64
#define NT    256
#define NT64  (S_LEN / 64)
#define TILEB 16384

// K/V pre-converted scratch: [B][tile][K,V][16KB] = 8MB (fp16)
__device__ __align__(16) char g_kv[4 * NT64 * 2 * TILEB];

// per-CTA smem byte offsets: Q | K0 K1 | V0 V1 | P0 P1
#define OQ     0
#define OK(p)  (16384 + (p) * 16384)
#define OV(p)  (49152 + (p) * 16384)
#define OP(p)  (81920 + (p) * 8192)
#define SMEM_BYTES 98304
#define ORS  16384
#define OSTG (16384 + 1024)

__device__ __forceinline__ uint32_t s2u(const void* p) {
    uint32_t a;
    asm("{ .reg .u64 t; cvta.to.shared.u64 t, %1; cvt.u32.u64 %0, t; }" : "=r"(a) : "l"(p));
    return a;
}
__device__ __forceinline__ void ldm4(uint32_t a, uint32_t* r) {
    asm volatile("ldmatrix.sync.aligned.m8n8.x4.shared.b16 {%0,%1,%2,%3}, [%4];"
                 : "=r"(r[0]), "=r"(r[1]), "=r"(r[2]), "=r"(r[3]) : "r"(a));
}
__device__ __forceinline__ void ldm4t(uint32_t a, uint32_t* r) {
    asm volatile("ldmatrix.sync.aligned.m8n8.x4.trans.shared.b16 {%0,%1,%2,%3}, [%4];"
                 : "=r"(r[0]), "=r"(r[1]), "=r"(r[2]), "=r"(r[3]) : "r"(a));
}
__device__ __forceinline__ void mma_f16(float* c, const uint32_t* a, uint32_t b0, uint32_t b1) {
    asm volatile("mma.sync.aligned.m16n8k16.row.col.f32.f16.f16.f32 "
                 "{%0,%1,%2,%3}, {%4,%5,%6,%7}, {%8,%9}, {%0,%1,%2,%3};"
                 : "+f"(c[0]), "+f"(c[1]), "+f"(c[2]), "+f"(c[3])
                 : "r"(a[0]), "r"(a[1]), "r"(a[2]), "r"(a[3]), "r"(b0), "r"(b1));
}
__device__ __forceinline__ uint32_t h2u(__half2 h) { return *reinterpret_cast<uint32_t*>(&h); }
__device__ __forceinline__ float ex2(float x) {
    float r;
    asm("ex2.approx.f32 %0, %1;" : "=f"(r) : "f"(x));
    return r;
}
__device__ __forceinline__ void cp16(uint32_t dst, const char* src) {
    asm volatile("cp.async.cg.shared.global [%0], [%1], 16;" :: "r"(dst), "l"(src));
}
#define CP_COMMIT() asm volatile("cp.async.commit_group;")
#define CP_WAIT0()  asm volatile("cp.async.wait_group 0;")
#define CP_WAIT1()  asm volatile("cp.async.wait_group 1;")

// ---- one QK kk-step: 1 A-ldm + up to 2 K-ldm + 4 MMA ----
__device__ __forceinline__ void qk_kk(float (*c)[4], uint32_t qb, uint32_t kb,
                                      bool sk0, bool sk1, uint32_t krow0, uint32_t krow1,
                                      int hi4, int lo7, int cbl, int kk) {
    uint32_t A[4];
    ldm4(qb + (uint32_t)(((2 * kk + hi4) ^ lo7) << 4), A);
    uint32_t kcol = (uint32_t)(((2 * kk + cbl) ^ lo7) << 4);
    if (!sk0) {
        uint32_t b0[4];
        ldm4(kb + krow0 + kcol, b0);
        mma_f16(c[0], A, b0[0], b0[1]); mma_f16(c[1], A, b0[2], b0[3]);
    }
    if (!sk1) {
        uint32_t b1[4];
        ldm4(kb + krow1 + kcol, b1);
        mma_f16(c[2], A, b1[0], b1[1]); mma_f16(c[3], A, b1[2], b1[3]);
    }
}

// ---- one PV chunk: 1 P-ldm + 4x(V-ldmt + 2 MMA) ----
__device__ __forceinline__ void pv_chunk(float (*o)[4], uint32_t pb, uint32_t vb,
                                         int hi4, int lo7, int nh, int kk2) {
    uint32_t ph[4];
    ldm4(pb + (uint32_t)(((2 * kk2 + hi4) ^ lo7) << 4), ph);
    uint32_t vrow = (uint32_t)(kk2 * 16 * 256);
    #pragma unroll
    for (int vp2 = 0; vp2 < 4; vp2++) {
        uint32_t bh[4];
        ldm4t(vb + vrow + (uint32_t)(((nh * 8 + 2 * vp2 + hi4) ^ lo7) << 4), bh);
        mma_f16(o[vp2 * 2],     ph, bh[0], bh[1]);
        mma_f16(o[vp2 * 2 + 1], ph, bh[2], bh[3]);
    }
}

// ================= pre-convert: K,V fp32 -> fp16 swizzled tile images =================
__global__ __launch_bounds__(NT, 4)
void conv_kv_kernel(const float* __restrict__ gk, const float* __restrict__ gv) {
    const int t = blockIdx.x, b = blockIdx.y, tid = threadIdx.x;
    char* dst = g_kv + ((size_t)(b * NT64 + t)) * 2 * TILEB;
    const float4* kg = reinterpret_cast<const float4*>(gk + ((size_t)b * S_LEN + t * 64) * DIM);
    const float4* vg = reinterpret_cast<const float4*>(gv + ((size_t)b * S_LEN + t * 64) * DIM);
    #pragma unroll
    for (int i = 0; i < 8; i++) {
        int idx = tid + i * NT;
        int row = idx >> 5, c4 = idx & 31;
        int chunk = c4 >> 1, sub = (c4 & 1) << 3;
        int off = row * 256 + ((chunk ^ (row & 7)) << 4) + sub;
        float4 kv = kg[idx];
        *reinterpret_cast<uint2*>(dst + off) =
            make_uint2(h2u(__floats2half2_rn(kv.x, kv.y)), h2u(__floats2half2_rn(kv.z, kv.w)));
        float4 vv = vg[idx];
        *reinterpret_cast<uint2*>(dst + TILEB + off) =
            make_uint2(h2u(__floats2half2_rn(vv.x, vv.y)), h2u(__floats2half2_rn(vv.z, vv.w)));
    }
}

// ================= main attention kernel =================
__global__ __launch_bounds__(NT, 2)
void swa_mma_kernel(const float* __restrict__ gq, const int* __restrict__ wptr,
                    float* __restrict__ gout)
{
    extern __shared__ char smc[];
    const uint32_t sb = s2u(smc);
    const int tid = threadIdx.x, lane = tid & 31, wr = tid >> 5;
    const int rg = wr & 3;
    const int nh = wr >> 2;
    const int q0 = blockIdx.x * BQ, b = blockIdx.y;
    const int w = wptr[0];
    const float scale = 1.44269504f * rsqrtf((float)DIM);

    const int il0 = rg * 16 + (lane >> 2);
    const int gr  = q0 + il0;
    const int hi4 = lane >> 4;
    const int lo7 = lane & 7;
    const int cbl = (lane >> 3) & 1;
    const int rbl = (lane & 7) + ((lane >> 4) << 3);

    const uint32_t qb    = sb + OQ + (uint32_t)((rg * 16 + (lane & 15)) * 256);
    const uint32_t pboff = (uint32_t)((rg * 16 + (lane & 15)) * 128);
    const uint32_t vboff = (uint32_t)((lane & 15) * 256);
    const uint32_t krow0 = (uint32_t)(((nh * 2 + 0) * 16 + rbl) * 256);
    const uint32_t krow1 = (uint32_t)(((nh * 2 + 1) * 16 + rbl) * 256);

    int lo = q0 - (w - 1);              if (lo < 0) lo = 0;
    int hi = q0 + BQ - 1 + (w - 1);     if (hi > S_LEN - 1) hi = S_LEN - 1;
    const int t0 = lo >> 6, t1 = hi >> 6;
    const int rlo = q0 + rg * 16, rhi = rlo + 15;

    const char* kvbase = g_kv + ((size_t)b * NT64) * 2 * TILEB;

    auto skq_of = [&](int k0t, int np2) {
        int kb0 = k0t + nh * 32 + np2 * 16;
        return (kb0 - rhi >= w) || (rlo - (kb0 + 15) >= w);
    };
    auto fiq_of = [&](int k0t, int np2) {     // fully inside band (no mask needed)
        int kb0 = k0t + nh * 32 + np2 * 16;
        return (rhi - kb0 < w) && (kb0 + 15 - rlo < w);
    };

    // ---- prologue: group A = {K(t0), V(t0)}; group B = {K(t0+1)} ----
    {
        const char* src = kvbase + (size_t)t0 * 2 * TILEB;
        #pragma unroll
        for (int i = 0; i < 4; i++) {
            int off = tid * 16 + i * 4096;
            cp16(sb + OK(t0 & 1) + off, src + off);
        }
        #pragma unroll
        for (int i = 0; i < 4; i++) {
            int off = tid * 16 + i * 4096;
            cp16(sb + OV(t0 & 1) + off, src + TILEB + off);
        }
        CP_COMMIT();
    }
    // Q -> smem (fp16, swizzled) — overlaps group A
    {
        const float4* qg = reinterpret_cast<const float4*>(gq + ((size_t)b * S_LEN + q0) * DIM);
        #pragma unroll
        for (int i = 0; i < 8; i++) {
            int idx = tid + i * NT;
            int row = idx >> 5, c4 = idx & 31;
            int chunk = c4 >> 1, sub = (c4 & 1) << 3;
            float4 vv = qg[idx];
            int off = row * 256 + ((chunk ^ (row & 7)) << 4) + sub;
            *reinterpret_cast<uint2*>(smc + OQ + off) =
                make_uint2(h2u(__floats2half2_rn(vv.x * scale, vv.y * scale)),
                           h2u(__floats2half2_rn(vv.z * scale, vv.w * scale)));
        }
    }
    if (t0 < t1) {
        const char* src = kvbase + (size_t)(t0 + 1) * 2 * TILEB;
        #pragma unroll
        for (int i = 0; i < 4; i++) {
            int off = tid * 16 + i * 4096;
            cp16(sb + OK((t0 + 1) & 1) + off, src + off);
        }
    }
    CP_COMMIT();

    float o[8][4];
    #pragma unroll
    for (int n = 0; n < 8; n++)
        #pragma unroll
        for (int e = 0; e < 4; e++) o[n][e] = 0.f;
    float c[4][4];
    #pragma unroll
    for (int n = 0; n < 4; n++)
        #pragma unroll
        for (int e = 0; e < 4; e++) c[n][e] = 0.f;
    float rs0 = 0.f, rs1 = 0.f;

    CP_WAIT1();                 // group A done
    __syncthreads();            // + Q visible

    // ---- QK(t0) ----
    bool sp0, sp1, fp0, fp1;
    {
        const int k0 = t0 << 6;
        sp0 = skq_of(k0, 0); sp1 = skq_of(k0, 1);
        fp0 = fiq_of(k0, 0); fp1 = fiq_of(k0, 1);
        #pragma unroll
        for (int kk = 0; kk < 8; kk++)
            qk_kk(c, qb, sb + OK(t0 & 1), sp0, sp1, krow0, krow1, hi4, lo7, cbl, kk);
    }

    for (int t = t0; t <= t1; t++) {
        const int k0 = t << 6;
        const int par = t & 1;
        const bool doQK = (t < t1);
        const int k0n = (t + 1) << 6;
        bool sq0 = doQK ? skq_of(k0n, 0) : true;
        bool sq1 = doQK ? skq_of(k0n, 1) : true;
        bool fq0 = doQK ? fiq_of(k0n, 0) : false;
        bool fq1 = doQK ? fiq_of(k0n, 1) : false;
        bool skp[4];
        #pragma unroll
        for (int kk2 = 0; kk2 < 4; kk2++) {
            int kb0 = k0 + kk2 * 16;
            skp[kk2] = (kb0 - rhi >= w) || (rlo - (kb0 + 15) >= w);
        }

        // ---- exp2 (+mask only on edge chunks) + thread-local rowsum partials ----
        #pragma unroll
        for (int h = 0; h < 2; h++) {
            const bool sp = h ? sp1 : sp0;
            const bool fp = h ? fp1 : fp0;
            if (!sp) {
                if (fp) {
                    #pragma unroll
                    for (int j = 2 * h; j < 2 * h + 2; j++) {
                        float e0 = ex2(c[j][0]), e1 = ex2(c[j][1]);
                        float e2 = ex2(c[j][2]), e3 = ex2(c[j][3]);
                        c[j][0] = e0; c[j][1] = e1; c[j][2] = e2; c[j][3] = e3;
                        rs0 += e0 + e1; rs1 += e2 + e3;
                    }
                } else {
                    #pragma unroll
                    for (int j = 2 * h; j < 2 * h + 2; j++) {
                        int jg = k0 + nh * 32 + j * 8 + ((lane & 3) << 1);
                        int d0 = gr - jg;
                        float e;
                        e = (d0 < w && d0 > -w)         ? ex2(c[j][0]) : 0.f; c[j][0] = e; rs0 += e;
                        e = (d0 - 1 < w && d0 - 1 > -w) ? ex2(c[j][1]) : 0.f; c[j][1] = e; rs0 += e;
                        e = (d0 + 8 < w && d0 + 8 > -w) ? ex2(c[j][2]) : 0.f; c[j][2] = e; rs1 += e;
                        e = (d0 + 7 < w && d0 + 7 > -w) ? ex2(c[j][3]) : 0.f; c[j][3] = e; rs1 += e;
                    }
                }
            }
        }

        // ---- P(t) -> P[par] ----
        #pragma unroll
        for (int j = 0; j < 4; j++) {
            if ((j < 2) ? sp0 : sp1) continue;
            int off0 = il0 * 128 + (((nh * 4 + j) ^ (il0 & 7)) << 4) + ((lane & 3) << 2);
            *reinterpret_cast<uint32_t*>(smc + OP(par) + off0) =
                h2u(__floats2half2_rn(c[j][0], c[j][1]));
            int r1 = il0 + 8;
            int off1 = r1 * 128 + (((nh * 4 + j) ^ (r1 & 7)) << 4) + ((lane & 3) << 2);
            *reinterpret_cast<uint32_t*>(smc + OP(par) + off1) =
                h2u(__floats2half2_rn(c[j][2], c[j][3]));
        }
        #pragma unroll
        for (int n = 0; n < 4; n++)
            #pragma unroll
            for (int e = 0; e < 4; e++) c[n][e] = 0.f;

        CP_WAIT0();                 // V(t), K(t+1) landed
        __syncthreads();            // single barrier per iteration

        // ---- post-barrier prefetch: {V(t+1), K(t+2)} one group ----
        if (t < t1) {
            const char* srcv = kvbase + (size_t)(t + 1) * 2 * TILEB;
            #pragma unroll
            for (int i = 0; i < 4; i++) {
                int off = tid * 16 + i * 4096;
                cp16(sb + OV((t + 1) & 1) + off, srcv + TILEB + off);
            }
            if (t + 2 <= t1) {
                const char* srck = kvbase + (size_t)(t + 2) * 2 * TILEB;
                #pragma unroll
                for (int i = 0; i < 4; i++) {
                    int off = tid * 16 + i * 4096;
                    cp16(sb + OK(par) + off, srck + off);
                }
            }
            CP_COMMIT();
        }

        // ---- fused MMA: fine interleave of QK(t+1) kk-steps and PV(t) chunks ----
        const uint32_t pb = sb + OP(par) + pboff;
        const uint32_t vb = sb + OV(par) + vboff;
        const uint32_t kbn = sb + OK((t + 1) & 1);
        #pragma unroll
        for (int i = 0; i < 4; i++) {
            if (doQK) {
                qk_kk(c, qb, kbn, sq0, sq1, krow0, krow1, hi4, lo7, cbl, 2 * i);
                qk_kk(c, qb, kbn, sq0, sq1, krow0, krow1, hi4, lo7, cbl, 2 * i + 1);
            }
            if (!skp[i])
                pv_chunk(o, pb, vb, hi4, lo7, nh, i);
        }

        sp0 = sq0; sp1 = sq1; fp0 = fq0; fp1 = fq1;
    }

    // ================= rowsum reduce (once) + combine + normalize + store =================
    rs0 += __shfl_xor_sync(0xffffffffu, rs0, 1);
    rs0 += __shfl_xor_sync(0xffffffffu, rs0, 2);
    rs1 += __shfl_xor_sync(0xffffffffu, rs1, 1);
    rs1 += __shfl_xor_sync(0xffffffffu, rs1, 2);
    __syncthreads();
    float* rsb = reinterpret_cast<float*>(smc + ORS);
    if ((lane & 3) == 0) {
        rsb[nh * 64 + il0]     = rs0;
        rsb[nh * 64 + il0 + 8] = rs1;
    }
    __syncthreads();
    const float inv0 = 1.0f / (rsb[il0]     + rsb[64 + il0]);
    const float inv1 = 1.0f / (rsb[il0 + 8] + rsb[64 + il0 + 8]);

    float* stg = reinterpret_cast<float*>(smc + OSTG);
    const int jd = (lane & 3) << 1;
    #pragma unroll
    for (int n = 0; n < 8; n++) {
        int col = nh * 64 + n * 8 + jd;
        *reinterpret_cast<float2*>(&stg[il0 * 132 + col]) =
            make_float2(o[n][0] * inv0, o[n][1] * inv0);
        *reinterpret_cast<float2*>(&stg[(il0 + 8) * 132 + col]) =
            make_float2(o[n][2] * inv1, o[n][3] * inv1);
    }
    __syncthreads();
    float4* og = reinterpret_cast<float4*>(gout + ((size_t)b * S_LEN + q0) * DIM);
    #pragma unroll
    for (int i = 0; i < 8; i++) {
        int idx = tid + i * NT;
        int row = idx >> 5, c4 = idx & 31;
        og[idx] = *reinterpret_cast<float4*>(&stg[row * 132 + c4 * 4]);
    }
}

extern "C" void kernel_launch(void* const* d_in, const int* in_sizes, int n_in,
                              void* d_out, int out_size) {
    const float* q = (const float*)d_in[0];
    const float* k = (const float*)d_in[1];
    const float* v = (const float*)d_in[2];
    const int*   w = (const int*)d_in[3];
    const int B = in_sizes[0] / (S_LEN * DIM);
    float* out = (float*)d_out;

    conv_kv_kernel<<<dim3(NT64, B), NT>>>(k, v);

    cudaFuncSetAttribute(swa_mma_kernel, cudaFuncAttributeMaxDynamicSharedMemorySize, SMEM_BYTES);
    dim3 grid(S_LEN / BQ, B);
    swa_mma_kernel<<<grid, NT, SMEM_BYTES>>>(q, w, out);
}